// round 11
// baseline (speedup 1.0000x reference)
#include <cuda_runtime.h>
#include <cuda_bf16.h>
#include <cstdint>
#include <math.h>

#define BB   4
#define CC   256
#define HH   128
#define WWp  128
#define HWS  16384      // HH*WWp
#define HEADS 8
#define CHD  32         // CC/HEADS
#define KQ   2304       // 9*CC for 3x3 conv as GEMM

// ---------------- scratch (device globals; no allocation) ----------------
__device__ __nv_bfloat16 g_xn  [BB*CC*HWS];          // LN(x) bf16 (kv GEMM B)
__device__ float         g_yn  [BB*CC*HWS];          // LN(y) fp32 (residual)
__device__ __nv_bfloat16 g_ynb [BB*CC*HWS];          // LN(y) bf16 (im2col source)
__device__ __nv_bfloat16 g_imq [(size_t)BB*KQ*HWS];  // im2col of yn (q GEMM B)
__device__ __nv_bfloat16 g_kvb [BB*2*CC*HWS];        // kv conv out bf16
__device__ __nv_bfloat16 g_kv2b[BB*2*CC*HWS];        // after depthwise, bf16
__device__ __nv_bfloat16 g_qb  [BB*CC*HWS];          // q conv out bf16
__device__ __nv_bfloat16 g_avb [BB*CC*HWS];          // attn@v bf16 (proj GEMM B)
__device__ float g_sumq[BB*CC];
__device__ float g_sumk[BB*CC];
__device__ float g_attn_part[8][BB*HEADS*CHD*CHD];
__device__ float g_attn[BB*HEADS*CHD*CHD];
// bf16 weights
__device__ __nv_bfloat16 g_Wkv[2*CC*CC];
__device__ __nv_bfloat16 g_Wq [CC*KQ];
__device__ __nv_bfloat16 g_Wp [CC*CC];

// ---------------- helpers ----------------
__device__ __forceinline__ uint32_t smem_u32(const void* p){
    uint32_t a;
    asm("{ .reg .u64 t; cvta.to.shared.u64 t, %1; cvt.u32.u64 %0, t; }" : "=r"(a) : "l"(p));
    return a;
}
#define SWZ(o) ((o) ^ (((o)>>3)&0x70))
#define CP_ASYNC16(dst, src) \
    asm volatile("cp.async.cg.shared.global [%0], [%1], 16;" :: "r"(dst), "l"(src))
#define CP_COMMIT() asm volatile("cp.async.commit_group;" ::: "memory")
#define CP_WAIT1()  asm volatile("cp.async.wait_group 1;" ::: "memory")
#define CP_WAIT0()  asm volatile("cp.async.wait_group 0;" ::: "memory")
#define MMA16816(c, a, b0, b1) \
    asm volatile("mma.sync.aligned.m16n8k16.row.col.f32.bf16.bf16.f32 " \
        "{%0,%1,%2,%3}, {%4,%5,%6,%7}, {%8,%9}, {%0,%1,%2,%3};" \
        : "+f"((c)[0]), "+f"((c)[1]), "+f"((c)[2]), "+f"((c)[3]) \
        : "r"((a)[0]), "r"((a)[1]), "r"((a)[2]), "r"((a)[3]), "r"(b0), "r"(b1))
#define LDSM_X4(r, addr) \
    asm volatile("ldmatrix.sync.aligned.m8n8.x4.shared.b16 {%0,%1,%2,%3}, [%4];" \
        : "=r"((r)[0]), "=r"((r)[1]), "=r"((r)[2]), "=r"((r)[3]) : "r"(addr))
#define LDSM_X4T(r, addr) \
    asm volatile("ldmatrix.sync.aligned.m8n8.x4.trans.shared.b16 {%0,%1,%2,%3}, [%4];" \
        : "=r"((r)[0]), "=r"((r)[1]), "=r"((r)[2]), "=r"((r)[3]) : "r"(addr))

// ---------------- 0. weight convert + zero norm accumulators ----------------
__global__ void convw_kernel(const float* __restrict__ Wkv, const float* __restrict__ Wq,
                             const float* __restrict__ Wp)
{
    int i = blockIdx.x*256 + threadIdx.x;
    if (i < 2*CC*CC) {                       // W_kv [512][256]
        g_Wkv[i] = __float2bfloat16(Wkv[i]);
    } else if (i < 2*CC*CC + CC*KQ) {        // W_q [256][256][3][3] -> [co][t*256+ci]
        int j = i - 2*CC*CC;
        int co = j / KQ, r = j % KQ;
        int t = r >> 8, ci = r & 255;
        g_Wq[j] = __float2bfloat16(Wq[((size_t)(co*CC+ci))*9 + t]);
    } else if (i < 2*CC*CC + CC*KQ + CC*CC) {
        int j = i - (2*CC*CC + CC*KQ);
        g_Wp[j] = __float2bfloat16(Wp[j]);
    } else {
        int j = i - (2*CC*CC + CC*KQ + CC*CC);
        if (j < BB*CC) g_sumq[j] = 0.f;
        else if (j < 2*BB*CC) g_sumk[j - BB*CC] = 0.f;
    }
}

// ---------------- 1. LayerNorm over channel dim ----------------
__global__ void ln_kernel(const float* __restrict__ x, const float* __restrict__ y,
                          const float* __restrict__ wkv, const float* __restrict__ bkv,
                          const float* __restrict__ wq,  const float* __restrict__ bq)
{
    int idx = blockIdx.x*blockDim.x + threadIdx.x;
    int b = idx >> 14;
    int p = idx & (HWS-1);
    size_t base = (size_t)b*CC*HWS + p;
    if (blockIdx.y == 0) {
        float s=0.f, s2=0.f;
        #pragma unroll 8
        for (int c=0;c<CC;c++){ float v = x[base + (size_t)c*HWS]; s+=v; s2+=v*v; }
        float mu = s*(1.f/CC), var = s2*(1.f/CC)-mu*mu, rs = rsqrtf(var+1e-5f);
        #pragma unroll 8
        for (int c=0;c<CC;c++){
            float v = x[base + (size_t)c*HWS];
            g_xn[base + (size_t)c*HWS] = __float2bfloat16((v-mu)*rs*wkv[c]+bkv[c]);
        }
    } else {
        float s=0.f, s2=0.f;
        #pragma unroll 8
        for (int c=0;c<CC;c++){ float v = y[base + (size_t)c*HWS]; s+=v; s2+=v*v; }
        float mu = s*(1.f/CC), var = s2*(1.f/CC)-mu*mu, rs = rsqrtf(var+1e-5f);
        #pragma unroll 8
        for (int c=0;c<CC;c++){
            float v = y[base + (size_t)c*HWS];
            float r = (v-mu)*rs*wq[c]+bq[c];
            g_yn [base + (size_t)c*HWS] = r;
            g_ynb[base + (size_t)c*HWS] = __float2bfloat16(r);
        }
    }
}

// ---------------- 2. im2col: 9 shifted bf16 copies of yn, 8 px/thread ----------------
__global__ void __launch_bounds__(256) shift9_kernel()
{
    int bx = blockIdx.x;                 // 0..71: tap*8 + seg
    int t = bx>>3, seg = bx&7;
    int ci = blockIdx.y, b = blockIdx.z;
    int tid = threadIdx.x;
    int px0 = seg*2048 + tid*8;
    int y = px0>>7, x0 = px0&127;
    int dy = t/3 - 1, dx = t%3 - 1;
    int yy = y + dy;
    const __nv_bfloat16* src = g_ynb + (((size_t)b*CC + ci)<<14);
    __nv_bfloat16 hv[8];
    if (yy>=0 && yy<HH){
        #pragma unroll
        for (int j=0;j<8;j++){
            int xx = x0 + j + dx;
            hv[j] = (xx>=0 && xx<WWp) ? src[yy*WWp+xx] : __float2bfloat16(0.f);
        }
    } else {
        #pragma unroll
        for (int j=0;j<8;j++) hv[j] = __float2bfloat16(0.f);
    }
    *(uint4*)(g_imq + (((size_t)b*KQ + t*CC + ci)<<14) + px0) = *(uint4*)hv;
}

// ---------------- 3. HMMA bf16 GEMM: out[b,m,n] = sum_k A[m,k]*B[b,k,n] -------------
// CTA tile M=128, N=128 (2 n-subtiles of 64), K chunk 64, double-buffered cp.async.
// 8 warps = 2(m) x 4(n), warp tile 64x32: 6 ldmatrix -> 16 MMAs per k16 step.
// Dynamic smem 64KB: A 2x16KB, B 2x16KB. grid=(m,n,b), m fastest for B L2 reuse.
template<bool OUTBF, bool SUMQ>
__global__ void __launch_bounds__(256, 2)
gemm_hmma(const __nv_bfloat16* __restrict__ A, const __nv_bfloat16* __restrict__ B,
          const float* __restrict__ R, void* __restrict__ outp,
          float* __restrict__ sumsq, int Kdim, int Mtotal)
{
    extern __shared__ __align__(1024) char smem[];
    const int tid = threadIdx.x;
    const int wid = tid>>5, lane = tid&31;
    const int gid = lane>>2, t4 = lane&3;
    const int b  = blockIdx.z;
    const int m0 = blockIdx.x*128;
    const int n0 = blockIdx.y*128;

    const uint32_t sbase = smem_u32(smem);
    const __nv_bfloat16* Ab = A + (size_t)m0*Kdim;
    const __nv_bfloat16* Bb = B + (size_t)b*Kdim*HWS + n0;

    const int mw = wid & 1;          // 2 m groups of 64
    const int nw = wid >> 1;         // 4 n groups of 32
    const int m0w = mw*64;
    const int sub = nw >> 1;         // which 64-col B subtile
    const int nloc = (nw & 1)*32;    // col offset within subtile

    const int l16 = lane & 15, lhi = (lane >> 4) * 16;
    uint32_t baseA[4];
    #pragma unroll
    for (int i=0;i<4;i++) baseA[i] = (uint32_t)((m0w + i*16 + l16)*128 + lhi);
    const uint32_t baseB0 = (uint32_t)(l16*128 + nloc*2 + lhi);
    const uint32_t baseB1 = (uint32_t)(l16*128 + (nloc+16)*2 + lhi);

    float acc[4][4][4] = {};
    const int nch = Kdim >> 6;       // K chunks of 64

    auto fill = [&](int k0, int st){
        uint32_t aA = sbase + st*16384;
        uint32_t aB = sbase + 32768 + st*16384;
        #pragma unroll
        for (int i=0;i<4;i++){       // A: 1024 16B chunks (128m x 64k)
            int e = tid + i*256;
            int m = e>>3, c8 = e&7;
            CP_ASYNC16(aA + SWZ(m*128 + c8*16), Ab + (size_t)m*Kdim + k0 + c8*8);
        }
        #pragma unroll
        for (int i=0;i<4;i++){       // B: 1024 16B chunks (64k x 128n, 2 subtiles)
            int e = tid + i*256;
            int k = e>>4, c16 = e&15, sb = c16>>3, c8 = c16&7;
            CP_ASYNC16(aB + sb*8192 + SWZ(k*128 + c8*16),
                       Bb + (size_t)(k0+k)*HWS + sb*64 + c8*8);
        }
    };

    fill(0, 0);
    CP_COMMIT();

    for (int c=0;c<nch;c++){
        if (c+1 < nch){ fill((c+1)<<6, (c+1)&1); CP_COMMIT(); CP_WAIT1(); }
        else          { CP_WAIT0(); }
        __syncthreads();
        const uint32_t aA = sbase + (c&1)*16384;
        const uint32_t aB = sbase + 32768 + (c&1)*16384 + sub*8192;
        #pragma unroll
        for (int ks=0; ks<4; ks++){
            uint32_t af[4][4], bf0[4], bf1[4];
            LDSM_X4T(bf0, aB + SWZ(baseB0 + ks*2048));
            LDSM_X4T(bf1, aB + SWZ(baseB1 + ks*2048));
            #pragma unroll
            for (int i=0;i<4;i++) LDSM_X4(af[i], aA + SWZ(baseA[i] + ks*32));
            #pragma unroll
            for (int i=0;i<4;i++){
                MMA16816(acc[i][0], af[i], bf0[0], bf0[1]);
                MMA16816(acc[i][1], af[i], bf0[2], bf0[3]);
                MMA16816(acc[i][2], af[i], bf1[0], bf1[1]);
                MMA16816(acc[i][3], af[i], bf1[2], bf1[3]);
            }
        }
        __syncthreads();
    }

    // epilogue
    #pragma unroll
    for (int i=0;i<4;i++){
        int r = m0 + m0w + i*16 + gid;
        #pragma unroll
        for (int j=0;j<4;j++){
            int col = n0 + nw*32 + j*8 + t4*2;
            size_t o0 = ((size_t)b*Mtotal + r)*HWS + col;
            size_t o1 = ((size_t)b*Mtotal + r + 8)*HWS + col;
            if (OUTBF){
                __nv_bfloat16* ob = (__nv_bfloat16*)outp;
                __nv_bfloat162 p0, p1;
                p0.x = __float2bfloat16(acc[i][j][0]);
                p0.y = __float2bfloat16(acc[i][j][1]);
                p1.x = __float2bfloat16(acc[i][j][2]);
                p1.y = __float2bfloat16(acc[i][j][3]);
                *(__nv_bfloat162*)&ob[o0] = p0;
                *(__nv_bfloat162*)&ob[o1] = p1;
            } else {
                float* of = (float*)outp;
                float2 v0 = make_float2(acc[i][j][0], acc[i][j][1]);
                float2 v1 = make_float2(acc[i][j][2], acc[i][j][3]);
                if (R){
                    float2 r0 = *(const float2*)&R[o0];
                    float2 r1 = *(const float2*)&R[o1];
                    v0.x += r0.x; v0.y += r0.y;
                    v1.x += r1.x; v1.y += r1.y;
                }
                *(float2*)&of[o0] = v0;
                *(float2*)&of[o1] = v1;
            }
        }
        if (SUMQ){
            float s0 = 0.f, s1 = 0.f;
            #pragma unroll
            for (int j=0;j<4;j++){
                s0 += acc[i][j][0]*acc[i][j][0] + acc[i][j][1]*acc[i][j][1];
                s1 += acc[i][j][2]*acc[i][j][2] + acc[i][j][3]*acc[i][j][3];
            }
            s0 += __shfl_xor_sync(0xffffffffu, s0, 1);
            s0 += __shfl_xor_sync(0xffffffffu, s0, 2);
            s1 += __shfl_xor_sync(0xffffffffu, s1, 1);
            s1 += __shfl_xor_sync(0xffffffffu, s1, 2);
            if (t4==0){
                atomicAdd(&sumsq[b*CC + r], s0);
                atomicAdd(&sumsq[b*CC + r + 8], s1);
            }
        }
    }
}

// ---------------- 4. depthwise 3x3 bf16, 8 px/thread, fused k-norm sums ----------------
__global__ void __launch_bounds__(256) dw_kernel(const float* __restrict__ Wdw)
{
    int bx = blockIdx.x;                 // 0..16383: bc*8 + seg
    int bc = bx>>3, seg = bx&7;
    int b = bc>>9, ch = bc&511;
    int tid = threadIdx.x;
    int px0 = seg*2048 + tid*8;
    int y = px0>>7, x0 = px0&127;
    const __nv_bfloat16* in = g_kvb + (size_t)bc*HWS;
    float w[9];
    #pragma unroll
    for (int i=0;i<9;i++) w[i] = __ldg(&Wdw[ch*9+i]);
    float buf[3][12];
    #pragma unroll
    for (int r=0;r<3;r++){
        int yy = y + r - 1;
        bool rowok = (yy>=0 && yy<HH);
        #pragma unroll
        for (int j=0;j<6;j++){
            int cx = x0 - 2 + 2*j;
            float vx = 0.f, vy = 0.f;
            if (rowok && cx>=0 && cx<WWp){
                __nv_bfloat162 t = *(const __nv_bfloat162*)(in + yy*WWp + cx);
                vx = __bfloat162float(t.x); vy = __bfloat162float(t.y);
            }
            buf[r][2*j] = vx; buf[r][2*j+1] = vy;
        }
    }
    __nv_bfloat16 hv[8];
    float s = 0.f;
    #pragma unroll
    for (int j=0;j<8;j++){
        float acc = 0.f;
        #pragma unroll
        for (int r=0;r<3;r++)
            #pragma unroll
            for (int d=0;d<3;d++)
                acc += w[r*3+d]*buf[r][j+1+d];
        hv[j] = __float2bfloat16(acc);
        float f = __bfloat162float(hv[j]);
        s += f*f;
    }
    *(uint4*)(g_kv2b + (size_t)bc*HWS + px0) = *(uint4*)hv;
    if (ch < 256){
        for (int o=16;o>0;o>>=1) s += __shfl_xor_sync(0xffffffffu, s, o);
        __shared__ float red[8];
        if ((tid&31)==0) red[tid>>5]=s;
        __syncthreads();
        if (tid<8){
            float v2 = red[tid];
            for (int o=4;o>0;o>>=1) v2 += __shfl_xor_sync(0x000000ffu, v2, o);
            if (tid==0) atomicAdd(&g_sumk[b*CC+ch], v2);
        }
    }
}

// ---------------- 6. attention scores: split-K QK^T partials (bf16 in) ----------------
__global__ void __launch_bounds__(256) attn_part_kernel()
{
    __shared__ float Qs[CHD][65];
    __shared__ float Kt[64][33];
    int bh = blockIdx.y;
    int b = bh >> 3, h = bh & 7;
    int split = blockIdx.x;
    int n0 = split*2048;
    const __nv_bfloat16* Qb = g_qb   + ((size_t)b*CC   + h*CHD)*HWS;
    const __nv_bfloat16* Kb = g_kv2b + ((size_t)b*2*CC + h*CHD)*HWS;
    int tid = threadIdx.x;
    int i = tid>>3, jq = tid&7;
    float acc[4]={};
    for (int nc=0;nc<2048;nc+=64){
        {
            int r = tid>>3, cg = (tid&7)*8;       // 256 threads = 32 r x 8 col-groups
            __nv_bfloat162 qv[4], kv[4];
            *(uint4*)qv = *(const uint4*)(Qb + (size_t)r*HWS + n0+nc+cg);
            *(uint4*)kv = *(const uint4*)(Kb + (size_t)r*HWS + n0+nc+cg);
            #pragma unroll
            for (int j2=0;j2<4;j2++){
                Qs[r][cg+2*j2]   = __bfloat162float(qv[j2].x);
                Qs[r][cg+2*j2+1] = __bfloat162float(qv[j2].y);
                Kt[cg+2*j2][r]   = __bfloat162float(kv[j2].x);
                Kt[cg+2*j2+1][r] = __bfloat162float(kv[j2].y);
            }
        }
        __syncthreads();
        #pragma unroll 8
        for (int cc=0;cc<64;cc++){
            float qv = Qs[i][cc];
            #pragma unroll
            for (int jj=0;jj<4;jj++) acc[jj] += qv * Kt[cc][jq*4+jj];
        }
        __syncthreads();
    }
    #pragma unroll
    for (int jj=0;jj<4;jj++)
        g_attn_part[split][bh*CHD*CHD + i*CHD + jq*4+jj] = acc[jj];
}

// ---------------- 7. combine partials, normalize, scale, softmax ----------------
__global__ void softmax_kernel(const float* __restrict__ temp)
{
    int bh = blockIdx.x;
    int b = bh>>3, h = bh&7;
    int tid = threadIdx.x;
    int i = tid>>5, j = tid&31;
    float v = 0.f;
    #pragma unroll
    for (int s=0;s<8;s++) v += g_attn_part[s][bh*1024 + i*32 + j];
    float iq = 1.f / fmaxf(sqrtf(g_sumq[b*CC + h*CHD + i]), 1e-12f);
    float ik = 1.f / fmaxf(sqrtf(g_sumk[b*CC + h*CHD + j]), 1e-12f);
    v *= iq * ik * temp[h];
    float m = v;
    for (int o=16;o>0;o>>=1) m = fmaxf(m, __shfl_xor_sync(0xffffffffu, m, o));
    float e = expf(v - m);
    float s = e;
    for (int o=16;o>0;o>>=1) s += __shfl_xor_sync(0xffffffffu, s, o);
    g_attn[bh*1024 + i*32 + j] = e / s;
}

// ---------------- 8. out = attn @ v  (bf16 in/out, 2 px/thread) ----------------
__global__ void __launch_bounds__(128) av_kernel()
{
    __shared__ float Amat[CHD][CHD];
    int bh = blockIdx.y; int b=bh>>3, h=bh&7;
    int n0 = blockIdx.x*256;
    int tid = threadIdx.x;
    for (int idx=tid; idx<CHD*CHD; idx+=128) ((float*)Amat)[idx] = g_attn[bh*1024+idx];
    __syncthreads();
    const __nv_bfloat16* Vb = g_kv2b + ((size_t)b*2*CC + CC + h*CHD)*HWS;
    float accx[CHD], accy[CHD];
    #pragma unroll
    for (int i=0;i<CHD;i++){ accx[i]=0.f; accy[i]=0.f; }
    int n = n0 + tid*2;
    #pragma unroll 4
    for (int j=0;j<CHD;j++){
        __nv_bfloat162 v2 = *(const __nv_bfloat162*)(Vb + (size_t)j*HWS + n);
        float vx = __bfloat162float(v2.x), vy = __bfloat162float(v2.y);
        #pragma unroll
        for (int i=0;i<CHD;i++){ accx[i] += Amat[i][j]*vx; accy[i] += Amat[i][j]*vy; }
    }
    __nv_bfloat16* Ob = g_avb + ((size_t)b*CC + h*CHD)*HWS;
    #pragma unroll
    for (int i=0;i<CHD;i++){
        __nv_bfloat162 o2;
        o2.x = __float2bfloat16(accx[i]);
        o2.y = __float2bfloat16(accy[i]);
        *(__nv_bfloat162*)(Ob + (size_t)i*HWS + n) = o2;
    }
}

// ---------------- launch ----------------
extern "C" void kernel_launch(void* const* d_in, const int* in_sizes, int n_in,
                              void* d_out, int out_size)
{
    const float* x       = (const float*)d_in[0];
    const float* y       = (const float*)d_in[1];
    const float* ln_kv_w = (const float*)d_in[2];
    const float* ln_kv_b = (const float*)d_in[3];
    const float* ln_q_w  = (const float*)d_in[4];
    const float* ln_q_b  = (const float*)d_in[5];
    const float* W_kv    = (const float*)d_in[6];
    const float* W_dw    = (const float*)d_in[7];
    const float* W_q     = (const float*)d_in[8];
    const float* W_proj  = (const float*)d_in[9];
    const float* temp    = (const float*)d_in[10];
    float* out = (float*)d_out;

    __nv_bfloat16 *p_xn, *p_imq, *p_avb, *p_Wkv, *p_Wq, *p_Wp, *p_kvb, *p_qb;
    float *p_yn, *p_sumq;
    cudaGetSymbolAddress((void**)&p_xn,   g_xn);
    cudaGetSymbolAddress((void**)&p_imq,  g_imq);
    cudaGetSymbolAddress((void**)&p_avb,  g_avb);
    cudaGetSymbolAddress((void**)&p_Wkv,  g_Wkv);
    cudaGetSymbolAddress((void**)&p_Wq,   g_Wq);
    cudaGetSymbolAddress((void**)&p_Wp,   g_Wp);
    cudaGetSymbolAddress((void**)&p_kvb,  g_kvb);
    cudaGetSymbolAddress((void**)&p_qb,   g_qb);
    cudaGetSymbolAddress((void**)&p_yn,   g_yn);
    cudaGetSymbolAddress((void**)&p_sumq, g_sumq);

    const int SMEM = 65536;
    cudaFuncSetAttribute(gemm_hmma<true,false>,  cudaFuncAttributeMaxDynamicSharedMemorySize, SMEM);
    cudaFuncSetAttribute(gemm_hmma<true,true>,   cudaFuncAttributeMaxDynamicSharedMemorySize, SMEM);
    cudaFuncSetAttribute(gemm_hmma<false,false>, cudaFuncAttributeMaxDynamicSharedMemorySize, SMEM);

    convw_kernel<<<3080, 256>>>(W_kv, W_q, W_proj);
    ln_kernel<<<dim3(256,2), 256>>>(x, y, ln_kv_w, ln_kv_b, ln_q_w, ln_q_b);
    shift9_kernel<<<dim3(72, CC, BB), 256>>>();
    // kv = W_kv @ xn   (M=512, K=256) -> bf16
    gemm_hmma<true,false><<<dim3(4, 128, BB), 256, SMEM>>>(p_Wkv, p_xn, nullptr, p_kvb, nullptr, CC, 2*CC);
    dw_kernel<<<16384, 256>>>(W_dw);
    // q = W_q(3x3) @ yn via im2col  (M=256, K=2304) -> bf16 + q-norm sums
    gemm_hmma<true,true><<<dim3(2, 128, BB), 256, SMEM>>>(p_Wq, p_imq, nullptr, p_qb, p_sumq, KQ, CC);
    attn_part_kernel<<<dim3(8,32), 256>>>();
    softmax_kernel<<<32, 1024>>>(temp);
    av_kernel<<<dim3(64,32), 128>>>();
    // out = yn + W_proj @ av  (M=256, K=256, residual) -> fp32
    gemm_hmma<false,false><<<dim3(2, 128, BB), 256, SMEM>>>(p_Wp, p_avb, p_yn, out, nullptr, CC, CC);
}

// round 14
// speedup vs baseline: 1.6512x; 1.6512x over previous
#include <cuda_runtime.h>
#include <cuda_bf16.h>
#include <cstdint>
#include <math.h>

#define BB   4
#define CC   256
#define HH   128
#define WWp  128
#define HWS  16384      // HH*WWp
#define HEADS 8
#define CHD  32         // CC/HEADS
#define KQ   2304       // 9*CC for 3x3 conv as GEMM
#define K3   768        // 3*CC (dx-only im2col)
#define PL   16640      // padded plane: 128 guard + 16384 + 128 guard

// ---------------- scratch (device globals; no allocation) ----------------
__device__ __nv_bfloat16 g_xn  [BB*CC*HWS];          // LN(x) bf16 (kv GEMM B)
__device__ float         g_yn  [BB*CC*HWS];          // LN(y) fp32 (residual)
__device__ __nv_bfloat16 g_ynb [BB*CC*HWS];          // LN(y) bf16 (im2col source)
__device__ __nv_bfloat16 g_im3 [(size_t)BB*K3*PL];   // 3 dx-shifted padded copies of yn
__device__ __nv_bfloat16 g_kvb [BB*2*CC*HWS];        // kv conv out bf16
__device__ __nv_bfloat16 g_kv2b[BB*2*CC*HWS];        // after depthwise, bf16
__device__ __nv_bfloat16 g_qb  [BB*CC*HWS];          // q conv out bf16
__device__ __nv_bfloat16 g_avb [BB*CC*HWS];          // attn@v bf16 (proj GEMM B)
__device__ float g_sumq[BB*CC];
__device__ float g_sumk[BB*CC];
__device__ float g_attn_part[8][BB*HEADS*CHD*CHD];
__device__ float g_attn[BB*HEADS*CHD*CHD];
// bf16 weights
__device__ __nv_bfloat16 g_Wkv[2*CC*CC];
__device__ __nv_bfloat16 g_Wq [CC*KQ];
__device__ __nv_bfloat16 g_Wp [CC*CC];

// ---------------- helpers ----------------
__device__ __forceinline__ uint32_t smem_u32(const void* p){
    uint32_t a;
    asm("{ .reg .u64 t; cvta.to.shared.u64 t, %1; cvt.u32.u64 %0, t; }" : "=r"(a) : "l"(p));
    return a;
}
#define SWZ(o) ((o) ^ (((o)>>3)&0x70))
#define CP_ASYNC16(dst, src) \
    asm volatile("cp.async.cg.shared.global [%0], [%1], 16;" :: "r"(dst), "l"(src))
#define CP_COMMIT() asm volatile("cp.async.commit_group;" ::: "memory")
#define CP_WAIT1()  asm volatile("cp.async.wait_group 1;" ::: "memory")
#define CP_WAIT0()  asm volatile("cp.async.wait_group 0;" ::: "memory")
#define MMA16816(c, a, b0, b1) \
    asm volatile("mma.sync.aligned.m16n8k16.row.col.f32.bf16.bf16.f32 " \
        "{%0,%1,%2,%3}, {%4,%5,%6,%7}, {%8,%9}, {%0,%1,%2,%3};" \
        : "+f"((c)[0]), "+f"((c)[1]), "+f"((c)[2]), "+f"((c)[3]) \
        : "r"((a)[0]), "r"((a)[1]), "r"((a)[2]), "r"((a)[3]), "r"(b0), "r"(b1))
#define LDSM_X4(r, addr) \
    asm volatile("ldmatrix.sync.aligned.m8n8.x4.shared.b16 {%0,%1,%2,%3}, [%4];" \
        : "=r"((r)[0]), "=r"((r)[1]), "=r"((r)[2]), "=r"((r)[3]) : "r"(addr))
#define LDSM_X4T(r, addr) \
    asm volatile("ldmatrix.sync.aligned.m8n8.x4.trans.shared.b16 {%0,%1,%2,%3}, [%4];" \
        : "=r"((r)[0]), "=r"((r)[1]), "=r"((r)[2]), "=r"((r)[3]) : "r"(addr))

// ---------------- 0. weight convert + zero norm accumulators ----------------
__global__ void convw_kernel(const float* __restrict__ Wkv, const float* __restrict__ Wq,
                             const float* __restrict__ Wp)
{
    int i = blockIdx.x*256 + threadIdx.x;
    if (i < 2*CC*CC) {                       // W_kv [512][256]
        g_Wkv[i] = __float2bfloat16(Wkv[i]);
    } else if (i < 2*CC*CC + CC*KQ) {        // W_q -> [co][dy*768 + dx*256 + ci]
        int j = i - 2*CC*CC;
        int co = j / KQ, r = j % KQ;
        int dy = r / K3, rem = r % K3;
        int dx = rem >> 8, ci = rem & 255;
        g_Wq[j] = __float2bfloat16(Wq[((size_t)(co*CC+ci))*9 + dy*3 + dx]);
    } else if (i < 2*CC*CC + CC*KQ + CC*CC) {
        int j = i - (2*CC*CC + CC*KQ);
        g_Wp[j] = __float2bfloat16(Wp[j]);
    } else {
        int j = i - (2*CC*CC + CC*KQ + CC*CC);
        if (j < BB*CC) g_sumq[j] = 0.f;
        else if (j < 2*BB*CC) g_sumk[j - BB*CC] = 0.f;
    }
}

// ---------------- 1. LayerNorm over channel dim (single-pass, smem tile) ----------------
__global__ void __launch_bounds__(256) ln_kernel(
    const float* __restrict__ x, const float* __restrict__ y,
    const float* __restrict__ wkv, const float* __restrict__ bkv,
    const float* __restrict__ wq,  const float* __restrict__ bq)
{
    __shared__ float s[CC][33];
    __shared__ float p1[8][32], p2[8][32];
    __shared__ float smu[32], srs[32];
    int b = blockIdx.x >> 9;
    int px0 = (blockIdx.x & 511) * 32;
    int tid = threadIdx.x;
    int px = tid & 31, grp = tid >> 5;
    bool isy = (blockIdx.y == 1);
    const float* src = isy ? y : x;
    size_t base = (size_t)b*CC*HWS + px0 + px;
    float sum=0.f, sum2=0.f;
    #pragma unroll 8
    for (int cc=0; cc<32; cc++){
        int c = grp*32 + cc;
        float v = src[base + (size_t)c*HWS];
        s[c][px] = v;
        sum += v; sum2 += v*v;
    }
    p1[grp][px] = sum; p2[grp][px] = sum2;
    __syncthreads();
    if (tid < 32){
        float S=0.f, S2=0.f;
        #pragma unroll
        for (int g=0; g<8; g++){ S += p1[g][tid]; S2 += p2[g][tid]; }
        float mu = S*(1.f/CC);
        float var = S2*(1.f/CC) - mu*mu;
        smu[tid] = mu;
        srs[tid] = rsqrtf(var + 1e-5f);
    }
    __syncthreads();
    float mu = smu[px], rs = srs[px];
    const float* wv = isy ? wq : wkv;
    const float* bv = isy ? bq : bkv;
    if (isy){
        #pragma unroll 8
        for (int cc=0; cc<32; cc++){
            int c = grp*32 + cc;
            float r = (s[c][px]-mu)*rs*__ldg(&wv[c]) + __ldg(&bv[c]);
            g_yn [base + (size_t)c*HWS] = r;
            g_ynb[base + (size_t)c*HWS] = __float2bfloat16(r);
        }
    } else {
        #pragma unroll 8
        for (int cc=0; cc<32; cc++){
            int c = grp*32 + cc;
            float r = (s[c][px]-mu)*rs*__ldg(&wv[c]) + __ldg(&bv[c]);
            g_xn[base + (size_t)c*HWS] = __float2bfloat16(r);
        }
    }
}

// ---------------- 2. im2col (dx shifts only) into padded planes ----------------
__global__ void __launch_bounds__(256) shift3_kernel()
{
    int bx = blockIdx.x;                 // 0..23: t*8 + seg
    int t = bx>>3, seg = bx&7;           // t = dx tap 0..2
    int ci = blockIdx.y, b = blockIdx.z;
    int tid = threadIdx.x;
    int p0 = seg*2048 + tid*8;
    int yq = p0>>7, x0 = p0&127;
    int dx = t - 1;
    const __nv_bfloat16* src = g_ynb + (((size_t)b*CC + ci)<<14);
    __nv_bfloat16* plane = g_im3 + (size_t)(b*K3 + t*CC + ci)*PL;
    __nv_bfloat16 hv[8];
    #pragma unroll
    for (int j=0;j<8;j++){
        int xx = x0 + j + dx;
        hv[j] = (xx>=0 && xx<WWp) ? src[yq*WWp+xx] : __float2bfloat16(0.f);
    }
    *(uint4*)(plane + 128 + p0) = *(uint4*)hv;
    // zero the guards
    if (seg==0 && tid<16){
        uint4 z = make_uint4(0,0,0,0);
        *(uint4*)(plane + tid*8) = z;
    }
    if (seg==7 && tid<16){
        uint4 z = make_uint4(0,0,0,0);
        *(uint4*)(plane + 16512 + tid*8) = z;
    }
}

// ---------------- 3. HMMA bf16 GEMM (round-9 config + dy-windowed B) -------------
// CTA tile M=128, N=64, K chunk 128 (2 halves of 64), double-buffered cp.async.
// 8 warps = 4(m) x 2(n), warp tile 32x32. Dynamic smem 96KB.
// B chunk c: dy = c/cpd, kk = (c%cpd)*128; row addr = Bb + (kk+k)*Bstride + dy*dyStep.
template<bool OUTBF, bool SUMQ>
__global__ void __launch_bounds__(256, 2)
gemm_hmma(const __nv_bfloat16* __restrict__ A, const __nv_bfloat16* __restrict__ B,
          const float* __restrict__ R, void* __restrict__ outp,
          float* __restrict__ sumsq, int Kdim, int Mtotal,
          int Bstride, int KtotB, int cpd, int dyStep)
{
    extern __shared__ __align__(1024) char smem[];
    const int tid = threadIdx.x;
    const int wid = tid>>5, lane = tid&31;
    const int gid = lane>>2, t4 = lane&3;
    const int b  = blockIdx.z;
    const int m0 = blockIdx.x*128;
    const int n0 = blockIdx.y*64;

    const uint32_t sbase = smem_u32(smem);
    const __nv_bfloat16* Ab = A + (size_t)m0*Kdim;
    const __nv_bfloat16* Bb0 = B + (size_t)b*KtotB*Bstride + n0;

    const int m0w = (wid&3)*32;      // warp m offset
    const int n0w = (wid>>2)*32;     // warp n offset

    const int l16 = lane & 15, lhi = (lane >> 4) * 16;
    const uint32_t baseA0 = (uint32_t)((m0w +      l16)*128 + lhi);
    const uint32_t baseA1 = (uint32_t)((m0w + 16 + l16)*128 + lhi);
    const uint32_t baseB0 = (uint32_t)(l16*128 + (n0w     )*2 + lhi);
    const uint32_t baseB1 = (uint32_t)(l16*128 + (n0w + 16)*2 + lhi);

    float acc[2][4][4] = {};
    const int nch = Kdim >> 7;       // K chunks of 128

    auto fill = [&](int c, int st){
        uint32_t aA = sbase + st*32768;
        uint32_t aB = sbase + 65536 + st*16384;
        int k0 = c<<7;
        int dy = c / cpd;
        int kk = (c - dy*cpd) << 7;
        const __nv_bfloat16* Bc = Bb0 + (size_t)kk*Bstride + (size_t)dy*dyStep;
        #pragma unroll
        for (int i=0;i<8;i++){       // A: 2048 16B chunks (128m x 128k)
            int e = tid + i*256;
            int m = e>>4, cc = e&15, half = cc>>3, c8 = cc&7;
            CP_ASYNC16(aA + half*16384 + SWZ(m*128 + c8*16),
                       Ab + (size_t)m*Kdim + k0 + half*64 + c8*8);
        }
        #pragma unroll
        for (int i=0;i<4;i++){       // B: 1024 16B chunks (128k x 64n)
            int e = tid + i*256;
            int k = e>>3, c8 = e&7, half = k>>6, kr = k&63;
            CP_ASYNC16(aB + half*8192 + SWZ(kr*128 + c8*16),
                       Bc + (size_t)k*Bstride + c8*8);
        }
    };

    fill(0, 0);
    CP_COMMIT();

    for (int c=0;c<nch;c++){
        if (c+1 < nch){ fill(c+1, (c+1)&1); CP_COMMIT(); CP_WAIT1(); }
        else          { CP_WAIT0(); }
        __syncthreads();
        const uint32_t aA = sbase + (c&1)*32768;
        const uint32_t aB = sbase + 65536 + (c&1)*16384;
        #pragma unroll
        for (int half=0; half<2; half++){
            const uint32_t hA = aA + half*16384;
            const uint32_t hB = aB + half*8192;
            #pragma unroll
            for (int ks=0; ks<4; ks++){
                uint32_t af0[4], af1[4], bf0[4], bf1[4];
                LDSM_X4 (af0, hA + SWZ(baseA0 + ks*32));
                LDSM_X4 (af1, hA + SWZ(baseA1 + ks*32));
                LDSM_X4T(bf0, hB + SWZ(baseB0 + ks*2048));
                LDSM_X4T(bf1, hB + SWZ(baseB1 + ks*2048));
                MMA16816(acc[0][0], af0, bf0[0], bf0[1]);
                MMA16816(acc[0][1], af0, bf0[2], bf0[3]);
                MMA16816(acc[0][2], af0, bf1[0], bf1[1]);
                MMA16816(acc[0][3], af0, bf1[2], bf1[3]);
                MMA16816(acc[1][0], af1, bf0[0], bf0[1]);
                MMA16816(acc[1][1], af1, bf0[2], bf0[3]);
                MMA16816(acc[1][2], af1, bf1[0], bf1[1]);
                MMA16816(acc[1][3], af1, bf1[2], bf1[3]);
            }
        }
        __syncthreads();
    }

    // epilogue
    #pragma unroll
    for (int mi=0; mi<2; mi++){
        int r = m0 + m0w + mi*16 + gid;
        #pragma unroll
        for (int ni=0; ni<4; ni++){
            int col = n0 + n0w + ni*8 + t4*2;
            size_t o0 = ((size_t)b*Mtotal + r)*HWS + col;
            size_t o1 = ((size_t)b*Mtotal + r + 8)*HWS + col;
            if (OUTBF){
                __nv_bfloat16* ob = (__nv_bfloat16*)outp;
                __nv_bfloat162 q0, q1;
                q0.x = __float2bfloat16(acc[mi][ni][0]);
                q0.y = __float2bfloat16(acc[mi][ni][1]);
                q1.x = __float2bfloat16(acc[mi][ni][2]);
                q1.y = __float2bfloat16(acc[mi][ni][3]);
                *(__nv_bfloat162*)&ob[o0] = q0;
                *(__nv_bfloat162*)&ob[o1] = q1;
            } else {
                float* of = (float*)outp;
                float2 v0 = make_float2(acc[mi][ni][0], acc[mi][ni][1]);
                float2 v1 = make_float2(acc[mi][ni][2], acc[mi][ni][3]);
                if (R){
                    float2 r0 = *(const float2*)&R[o0];
                    float2 r1 = *(const float2*)&R[o1];
                    v0.x += r0.x; v0.y += r0.y;
                    v1.x += r1.x; v1.y += r1.y;
                }
                *(float2*)&of[o0] = v0;
                *(float2*)&of[o1] = v1;
            }
        }
        if (SUMQ){
            float s0 = 0.f, s1 = 0.f;
            #pragma unroll
            for (int ni=0; ni<4; ni++){
                s0 += acc[mi][ni][0]*acc[mi][ni][0] + acc[mi][ni][1]*acc[mi][ni][1];
                s1 += acc[mi][ni][2]*acc[mi][ni][2] + acc[mi][ni][3]*acc[mi][ni][3];
            }
            s0 += __shfl_xor_sync(0xffffffffu, s0, 1);
            s0 += __shfl_xor_sync(0xffffffffu, s0, 2);
            s1 += __shfl_xor_sync(0xffffffffu, s1, 1);
            s1 += __shfl_xor_sync(0xffffffffu, s1, 2);
            if (t4==0){
                atomicAdd(&sumsq[b*CC + r], s0);
                atomicAdd(&sumsq[b*CC + r + 8], s1);
            }
        }
    }
}

// ---------------- 4. depthwise 3x3 bf16, 8 px/thread, fused k-norm sums ----------------
__global__ void __launch_bounds__(256) dw_kernel(const float* __restrict__ Wdw)
{
    int bx = blockIdx.x;                 // 0..16383: bc*8 + seg
    int bc = bx>>3, seg = bx&7;
    int b = bc>>9, ch = bc&511;
    int tid = threadIdx.x;
    int px0 = seg*2048 + tid*8;
    int y = px0>>7, x0 = px0&127;
    const __nv_bfloat16* in = g_kvb + (size_t)bc*HWS;
    float w[9];
    #pragma unroll
    for (int i=0;i<9;i++) w[i] = __ldg(&Wdw[ch*9+i]);
    float buf[3][12];
    #pragma unroll
    for (int r=0;r<3;r++){
        int yy = y + r - 1;
        bool rowok = (yy>=0 && yy<HH);
        #pragma unroll
        for (int j=0;j<6;j++){
            int cx = x0 - 2 + 2*j;
            float vx = 0.f, vy = 0.f;
            if (rowok && cx>=0 && cx<WWp){
                __nv_bfloat162 t = *(const __nv_bfloat162*)(in + yy*WWp + cx);
                vx = __bfloat162float(t.x); vy = __bfloat162float(t.y);
            }
            buf[r][2*j] = vx; buf[r][2*j+1] = vy;
        }
    }
    __nv_bfloat16 hv[8];
    float s = 0.f;
    #pragma unroll
    for (int j=0;j<8;j++){
        float acc = 0.f;
        #pragma unroll
        for (int r=0;r<3;r++)
            #pragma unroll
            for (int d=0;d<3;d++)
                acc += w[r*3+d]*buf[r][j+1+d];
        hv[j] = __float2bfloat16(acc);
        float f = __bfloat162float(hv[j]);
        s += f*f;
    }
    *(uint4*)(g_kv2b + (size_t)bc*HWS + px0) = *(uint4*)hv;
    if (ch < 256){
        for (int o=16;o>0;o>>=1) s += __shfl_xor_sync(0xffffffffu, s, o);
        __shared__ float red[8];
        if ((tid&31)==0) red[tid>>5]=s;
        __syncthreads();
        if (tid<8){
            float v2 = red[tid];
            for (int o=4;o>0;o>>=1) v2 += __shfl_xor_sync(0x000000ffu, v2, o);
            if (tid==0) atomicAdd(&g_sumk[b*CC+ch], v2);
        }
    }
}

// ---------------- 6. attention scores: split-K QK^T partials (bf16 in) ----------------
__global__ void __launch_bounds__(256) attn_part_kernel()
{
    __shared__ float Qs[CHD][65];
    __shared__ float Kt[64][33];
    int bh = blockIdx.y;
    int b = bh >> 3, h = bh & 7;
    int split = blockIdx.x;
    int n0 = split*2048;
    const __nv_bfloat16* Qb = g_qb   + ((size_t)b*CC   + h*CHD)*HWS;
    const __nv_bfloat16* Kb = g_kv2b + ((size_t)b*2*CC + h*CHD)*HWS;
    int tid = threadIdx.x;
    int i = tid>>3, jq = tid&7;
    float acc[4]={};
    for (int nc=0;nc<2048;nc+=64){
        {
            int r = tid>>3, cg = (tid&7)*8;
            __nv_bfloat162 qv[4], kv[4];
            *(uint4*)qv = *(const uint4*)(Qb + (size_t)r*HWS + n0+nc+cg);
            *(uint4*)kv = *(const uint4*)(Kb + (size_t)r*HWS + n0+nc+cg);
            #pragma unroll
            for (int j2=0;j2<4;j2++){
                Qs[r][cg+2*j2]   = __bfloat162float(qv[j2].x);
                Qs[r][cg+2*j2+1] = __bfloat162float(qv[j2].y);
                Kt[cg+2*j2][r]   = __bfloat162float(kv[j2].x);
                Kt[cg+2*j2+1][r] = __bfloat162float(kv[j2].y);
            }
        }
        __syncthreads();
        #pragma unroll 8
        for (int cc=0;cc<64;cc++){
            float qv = Qs[i][cc];
            #pragma unroll
            for (int jj=0;jj<4;jj++) acc[jj] += qv * Kt[cc][jq*4+jj];
        }
        __syncthreads();
    }
    #pragma unroll
    for (int jj=0;jj<4;jj++)
        g_attn_part[split][bh*CHD*CHD + i*CHD + jq*4+jj] = acc[jj];
}

// ---------------- 7. combine partials, normalize, scale, softmax ----------------
__global__ void softmax_kernel(const float* __restrict__ temp)
{
    int bh = blockIdx.x;
    int b = bh>>3, h = bh&7;
    int tid = threadIdx.x;
    int i = tid>>5, j = tid&31;
    float v = 0.f;
    #pragma unroll
    for (int s=0;s<8;s++) v += g_attn_part[s][bh*1024 + i*32 + j];
    float iq = 1.f / fmaxf(sqrtf(g_sumq[b*CC + h*CHD + i]), 1e-12f);
    float ik = 1.f / fmaxf(sqrtf(g_sumk[b*CC + h*CHD + j]), 1e-12f);
    v *= iq * ik * temp[h];
    float m = v;
    for (int o=16;o>0;o>>=1) m = fmaxf(m, __shfl_xor_sync(0xffffffffu, m, o));
    float e = expf(v - m);
    float s = e;
    for (int o=16;o>0;o>>=1) s += __shfl_xor_sync(0xffffffffu, s, o);
    g_attn[bh*1024 + i*32 + j] = e / s;
}

// ---------------- 8. out = attn @ v  (bf16 in/out, 2 px/thread) ----------------
__global__ void __launch_bounds__(128) av_kernel()
{
    __shared__ float Amat[CHD][CHD];
    int bh = blockIdx.y; int b=bh>>3, h=bh&7;
    int n0 = blockIdx.x*256;
    int tid = threadIdx.x;
    for (int idx=tid; idx<CHD*CHD; idx+=128) ((float*)Amat)[idx] = g_attn[bh*1024+idx];
    __syncthreads();
    const __nv_bfloat16* Vb = g_kv2b + ((size_t)b*2*CC + CC + h*CHD)*HWS;
    float accx[CHD], accy[CHD];
    #pragma unroll
    for (int i=0;i<CHD;i++){ accx[i]=0.f; accy[i]=0.f; }
    int n = n0 + tid*2;
    #pragma unroll 4
    for (int j=0;j<CHD;j++){
        __nv_bfloat162 v2 = *(const __nv_bfloat162*)(Vb + (size_t)j*HWS + n);
        float vx = __bfloat162float(v2.x), vy = __bfloat162float(v2.y);
        #pragma unroll
        for (int i=0;i<CHD;i++){ accx[i] += Amat[i][j]*vx; accy[i] += Amat[i][j]*vy; }
    }
    __nv_bfloat16* Ob = g_avb + ((size_t)b*CC + h*CHD)*HWS;
    #pragma unroll
    for (int i=0;i<CHD;i++){
        __nv_bfloat162 o2;
        o2.x = __float2bfloat16(accx[i]);
        o2.y = __float2bfloat16(accy[i]);
        *(__nv_bfloat162*)(Ob + (size_t)i*HWS + n) = o2;
    }
}

// ---------------- launch ----------------
extern "C" void kernel_launch(void* const* d_in, const int* in_sizes, int n_in,
                              void* d_out, int out_size)
{
    const float* x       = (const float*)d_in[0];
    const float* y       = (const float*)d_in[1];
    const float* ln_kv_w = (const float*)d_in[2];
    const float* ln_kv_b = (const float*)d_in[3];
    const float* ln_q_w  = (const float*)d_in[4];
    const float* ln_q_b  = (const float*)d_in[5];
    const float* W_kv    = (const float*)d_in[6];
    const float* W_dw    = (const float*)d_in[7];
    const float* W_q     = (const float*)d_in[8];
    const float* W_proj  = (const float*)d_in[9];
    const float* temp    = (const float*)d_in[10];
    float* out = (float*)d_out;

    __nv_bfloat16 *p_xn, *p_im3, *p_avb, *p_Wkv, *p_Wq, *p_Wp, *p_kvb, *p_qb;
    float *p_yn, *p_sumq;
    cudaGetSymbolAddress((void**)&p_xn,   g_xn);
    cudaGetSymbolAddress((void**)&p_im3,  g_im3);
    cudaGetSymbolAddress((void**)&p_avb,  g_avb);
    cudaGetSymbolAddress((void**)&p_Wkv,  g_Wkv);
    cudaGetSymbolAddress((void**)&p_Wq,   g_Wq);
    cudaGetSymbolAddress((void**)&p_Wp,   g_Wp);
    cudaGetSymbolAddress((void**)&p_kvb,  g_kvb);
    cudaGetSymbolAddress((void**)&p_qb,   g_qb);
    cudaGetSymbolAddress((void**)&p_yn,   g_yn);
    cudaGetSymbolAddress((void**)&p_sumq, g_sumq);

    const int SMEM = 98304;
    cudaFuncSetAttribute(gemm_hmma<true,false>,  cudaFuncAttributeMaxDynamicSharedMemorySize, SMEM);
    cudaFuncSetAttribute(gemm_hmma<true,true>,   cudaFuncAttributeMaxDynamicSharedMemorySize, SMEM);
    cudaFuncSetAttribute(gemm_hmma<false,false>, cudaFuncAttributeMaxDynamicSharedMemorySize, SMEM);

    convw_kernel<<<3080, 256>>>(W_kv, W_q, W_proj);
    ln_kernel<<<dim3(2048,2), 256>>>(x, y, ln_kv_w, ln_kv_b, ln_q_w, ln_q_b);
    shift3_kernel<<<dim3(24, CC, BB), 256>>>();
    // kv = W_kv @ xn   (M=512, K=256) -> bf16
    gemm_hmma<true,false><<<dim3(4, 256, BB), 256, SMEM>>>(
        p_Wkv, p_xn, nullptr, p_kvb, nullptr, CC, 2*CC, HWS, CC, 2, 0);
    dw_kernel<<<16384, 256>>>(W_dw);
    // q = W_q(3x3) @ yn, K=2304 = 3 dy x 768, B windows into padded planes
    gemm_hmma<true,true><<<dim3(2, 256, BB), 256, SMEM>>>(
        p_Wq, p_im3, nullptr, p_qb, p_sumq, KQ, CC, PL, K3, 6, 128);
    attn_part_kernel<<<dim3(8,32), 256>>>();
    softmax_kernel<<<32, 1024>>>(temp);
    av_kernel<<<dim3(64,32), 128>>>();
    // out = yn + W_proj @ av  (M=256, K=256, residual) -> fp32
    gemm_hmma<false,false><<<dim3(2, 256, BB), 256, SMEM>>>(
        p_Wp, p_avb, p_yn, out, nullptr, CC, CC, HWS, CC, 2, 0);
}